// round 1
// baseline (speedup 1.0000x reference)
#include <cuda_runtime.h>
#include <math.h>

#define B 128
#define LSEQ 4096
#define NF 2049          // rfft bins
#define L1E 1025         // expert conv1 out length
#define L2E 513          // expert conv2/conv3 out length
#define NTASK 256        // B * TOP_K

// ---------------- scratch (device globals; no allocations allowed) -------------
__device__ float g_fft[B * 2 * NF];          // windowed rfft, [b][re/im][f]
__device__ float g_h1 [B * 32 * NF];         // gate conv1 out
__device__ float g_pooled[B * 64];           // gate conv2 mean-pool accum
__device__ float g_tw[NTASK];                // normalized top-2 weights
__device__ int   g_ti[NTASK];                // top-2 expert ids
__device__ float g_e1[NTASK * 64  * L1E];
__device__ float g_e2[NTASK * 128 * L2E];
__device__ float g_e3[NTASK * 128 * L2E];

// ---------------- 1) Hann window + 4096-pt radix-2 FFT (one block per row) -----
__global__ void fft_kernel(const float* __restrict__ x) {
    __shared__ float re[4096];
    __shared__ float im[4096];
    int b = blockIdx.x;
    const float* xb = x + b * LSEQ;

    for (int i = threadIdx.x; i < 4096; i += blockDim.x) {
        float w = 0.5f * (1.0f - cospif((float)i * (1.0f / 2048.0f)));
        int j = __brev((unsigned)i) >> 20;   // 12-bit reversal
        re[j] = xb[i] * w;
        im[j] = 0.0f;
    }
    __syncthreads();

    for (int s = 1; s <= 12; s++) {
        int half = 1 << (s - 1);
        int len  = 1 << s;
        for (int t = threadIdx.x; t < 2048; t += blockDim.x) {
            int g   = t >> (s - 1);
            int pos = t & (half - 1);
            int i0  = g * len + pos;
            int i1  = i0 + half;
            float ang = -2.0f * (float)pos / (float)len;   // in units of pi
            float si, sr;
            sincospif(ang, &si, &sr);                      // twiddle = sr + i*si
            float ar = re[i1], ai = im[i1];
            float tr = ar * sr - ai * si;
            float ti = ar * si + ai * sr;
            float br = re[i0], bi = im[i0];
            re[i1] = br - tr; im[i1] = bi - ti;
            re[i0] = br + tr; im[i0] = bi + ti;
        }
        __syncthreads();
    }
    const float sc = 1.0f / 64.0f;   // ortho norm: 1/sqrt(4096)
    for (int f = threadIdx.x; f < NF; f += blockDim.x) {
        g_fft[(b * 2 + 0) * NF + f] = re[f] * sc;
        g_fft[(b * 2 + 1) * NF + f] = im[f] * sc;
    }
}

// ---------------- 2) gate conv1: (2 -> 32), k=5, s=1, p=2, relu ----------------
__global__ void gconv1_kernel(const float* __restrict__ w1, const float* __restrict__ b1) {
    __shared__ float sin_[2][132];
    __shared__ float sw[320];
    __shared__ float sb[32];
    int b  = blockIdx.y;
    int l0 = blockIdx.x * 128;
    int tid = threadIdx.x;   // 128

    for (int i = tid; i < 320; i += 128) sw[i] = w1[i];
    if (tid < 32) sb[tid] = b1[tid];
    for (int i = tid; i < 264; i += 128) {
        int ci = i / 132, j = i % 132;
        int g = l0 + j - 2;
        sin_[ci][j] = (g >= 0 && g < NF) ? g_fft[(b * 2 + ci) * NF + g] : 0.0f;
    }
    __syncthreads();

    int l = l0 + tid;
    if (l < NF) {
        #pragma unroll 4
        for (int co = 0; co < 32; co++) {
            float acc = sb[co];
            #pragma unroll
            for (int ci = 0; ci < 2; ci++)
                #pragma unroll
                for (int k = 0; k < 5; k++)
                    acc += sin_[ci][tid + k] * sw[co * 10 + ci * 5 + k];
            g_h1[(b * 32 + co) * NF + l] = fmaxf(acc, 0.0f);
        }
    }
}

__global__ void zero_pooled_kernel() {
    int i = blockIdx.x * blockDim.x + threadIdx.x;
    if (i < B * 64) g_pooled[i] = 0.0f;
}

// ---------------- 3) gate conv2 (32 -> 64, k5, p2) fused with mean pool --------
// grid (17 lchunks, B, 2 co-halves), 256 threads; 4co x 4l register tile.
__global__ void gconv2_pool_kernel(const float* __restrict__ w2, const float* __restrict__ b2) {
    __shared__ float sin_[32][132];
    __shared__ float sw[32 * 161];     // pitch 161 to break bank collisions
    int b   = blockIdx.y;
    int l0  = blockIdx.x * 128;
    int ch  = blockIdx.z;              // co base = ch*32
    int tid = threadIdx.x;             // 256
    int lg  = tid & 31;
    int cg  = tid >> 5;                // 0..7 -> 4 co each

    for (int i = tid; i < 32 * 132; i += 256) {
        int ci = i / 132, j = i % 132;
        int g = l0 + j - 2;
        sin_[ci][j] = (g >= 0 && g < NF) ? g_h1[(b * 32 + ci) * NF + g] : 0.0f;
    }
    for (int i = tid; i < 32 * 160; i += 256) {
        int co = i / 160, r = i % 160;
        sw[co * 161 + r] = w2[(ch * 32 + co) * 160 + r];
    }
    __syncthreads();

    float acc[4][4];
    #pragma unroll
    for (int j = 0; j < 4; j++)
        #pragma unroll
        for (int i = 0; i < 4; i++) acc[j][i] = 0.0f;

    #pragma unroll 4
    for (int ci = 0; ci < 32; ci++) {
        float v[4][5];
        #pragma unroll
        for (int i = 0; i < 4; i++)
            #pragma unroll
            for (int k = 0; k < 5; k++)
                v[i][k] = sin_[ci][lg + 32 * i + k];
        #pragma unroll
        for (int j = 0; j < 4; j++)
            #pragma unroll
            for (int k = 0; k < 5; k++) {
                float w = sw[(cg * 4 + j) * 161 + ci * 5 + k];
                #pragma unroll
                for (int i = 0; i < 4; i++)
                    acc[j][i] += w * v[i][k];
            }
    }

    #pragma unroll
    for (int j = 0; j < 4; j++) {
        int cog = ch * 32 + cg * 4 + j;
        float bias = b2[cog];
        float part = 0.0f;
        #pragma unroll
        for (int i = 0; i < 4; i++) {
            int l = l0 + lg + 32 * i;
            if (l < NF) part += fmaxf(acc[j][i] + bias, 0.0f);
        }
        #pragma unroll
        for (int off = 16; off; off >>= 1)
            part += __shfl_down_sync(0xffffffffu, part, off, 32);
        if (lg == 0) atomicAdd(&g_pooled[b * 64 + cog], part);
    }
}

// ---------------- 4) router MLP + softmax + top2 + aux (one block) -------------
__global__ void gate_mlp_kernel(const float* __restrict__ w1, const float* __restrict__ b1,
                                const float* __restrict__ w2, const float* __restrict__ b2,
                                float* __restrict__ out, int out_size) {
    int b = threadIdx.x;   // 128
    const float inv = 1.0f / 2049.0f;
    float p[64];
    #pragma unroll
    for (int i = 0; i < 64; i++) p[i] = g_pooled[b * 64 + i] * inv;

    float lg[8];
    #pragma unroll
    for (int e = 0; e < 8; e++) lg[e] = b2[e];

    for (int j = 0; j < 128; j++) {
        float h0 = 0.f, h1 = 0.f, h2 = 0.f, h3 = 0.f;
        #pragma unroll
        for (int i = 0; i < 64; i += 4) {
            h0 += p[i + 0] * w1[j * 64 + i + 0];
            h1 += p[i + 1] * w1[j * 64 + i + 1];
            h2 += p[i + 2] * w1[j * 64 + i + 2];
            h3 += p[i + 3] * w1[j * 64 + i + 3];
        }
        float h = fmaxf((h0 + h1) + (h2 + h3) + b1[j], 0.0f);
        #pragma unroll
        for (int e = 0; e < 8; e++) lg[e] += h * w2[e * 128 + j];
    }

    float m = lg[0];
    #pragma unroll
    for (int e = 1; e < 8; e++) m = fmaxf(m, lg[e]);
    float rw[8], s = 0.0f;
    #pragma unroll
    for (int e = 0; e < 8; e++) { rw[e] = expf(lg[e] - m); s += rw[e]; }
    float invs = 1.0f / s;
    #pragma unroll
    for (int e = 0; e < 8; e++) rw[e] *= invs;

    int i0 = 0;
    #pragma unroll
    for (int e = 1; e < 8; e++) if (rw[e] > rw[i0]) i0 = e;
    int i1 = (i0 == 0) ? 1 : 0;
    #pragma unroll
    for (int e = 0; e < 8; e++) if (e != i1 && e != i0 && rw[e] > rw[i1]) i1 = e;

    float t0 = rw[i0], t1 = rw[i1];
    float tn = 1.0f / (t0 + t1);
    g_ti[b * 2 + 0] = i0; g_ti[b * 2 + 1] = i1;
    g_tw[b * 2 + 0] = t0 * tn; g_tw[b * 2 + 1] = t1 * tn;

    __shared__ float srw[8], slg[8];
    if (b < 8) { srw[b] = 0.0f; slg[b] = 0.0f; }
    __syncthreads();
    #pragma unroll
    for (int e = 0; e < 8; e++) {
        atomicAdd(&srw[e], rw[e]);
        atomicAdd(&slg[e], lg[e]);
    }
    __syncthreads();
    if (b == 0) {
        float aux = 0.0f;
        #pragma unroll
        for (int e = 0; e < 8; e++)
            aux += (srw[e] * (1.0f / 128.0f)) * (slg[e] * (1.0f / 128.0f));
        out[out_size - 1] = 0.01f * 8.0f * aux;
    }
}

// ---------------- 5) expert conv1: (2 -> 64), k=7, s=2, p=3, relu --------------
__global__ void econv1_kernel(const float* __restrict__ ew1, const float* __restrict__ eb1) {
    __shared__ float sin_[2][2056];
    __shared__ float sw[64 * 14];
    __shared__ float sb[64];
    int t = blockIdx.x;
    int b = t >> 1;
    int e = g_ti[t];
    int tid = threadIdx.x;   // 256

    for (int i = tid; i < 2 * 2056; i += 256) {
        int ci = i / 2056, j = i % 2056;
        int g = j - 3;
        sin_[ci][j] = (g >= 0 && g < NF) ? g_fft[(b * 2 + ci) * NF + g] : 0.0f;
    }
    for (int i = tid; i < 64 * 14; i += 256) sw[i] = ew1[e * 64 * 14 + i];
    if (tid < 64) sb[tid] = eb1[e * 64 + tid];
    __syncthreads();

    for (int co = 0; co < 64; co++) {
        float bias = sb[co];
        for (int l = tid; l < L1E; l += 256) {
            float acc = bias;
            #pragma unroll
            for (int ci = 0; ci < 2; ci++)
                #pragma unroll
                for (int k = 0; k < 7; k++)
                    acc += sin_[ci][2 * l + k] * sw[co * 14 + ci * 7 + k];
            g_e1[(t * 64 + co) * L1E + l] = fmaxf(acc, 0.0f);
        }
    }
}

// ---------------- 6) expert conv2: (64 -> 128), k=5, s=2, p=2, relu ------------
// grid (5 lchunks, 8 co-groups, 256 tasks), 128 threads; 4co x 4l tile, ci in 2 halves.
__global__ void econv2_kernel(const float* __restrict__ ew2, const float* __restrict__ eb2) {
    __shared__ float sin_[32][260];
    __shared__ float sw[16 * 161];
    int t  = blockIdx.z;
    int e  = g_ti[t];
    int l0 = blockIdx.x * 128;
    int cg = blockIdx.y;        // co base cg*16
    int tid = threadIdx.x;
    int lg  = tid & 31;
    int cidx = tid >> 5;        // 0..3 -> 4 co each

    float acc[4][4];
    #pragma unroll
    for (int j = 0; j < 4; j++)
        #pragma unroll
        for (int i = 0; i < 4; i++) acc[j][i] = 0.0f;

    const float* e1base = g_e1 + (size_t)t * 64 * L1E;

    for (int cb = 0; cb < 2; cb++) {
        __syncthreads();
        for (int i = tid; i < 32 * 259; i += 128) {
            int ci = i / 259, j = i % 259;
            int g = 2 * l0 - 2 + j;
            sin_[ci][j] = (g >= 0 && g < L1E) ? e1base[(cb * 32 + ci) * L1E + g] : 0.0f;
        }
        for (int i = tid; i < 16 * 160; i += 128) {
            int co = i / 160, r = i % 160;
            sw[co * 161 + r] = ew2[((e * 128 + cg * 16 + co) * 64 + cb * 32) * 5 + r];
        }
        __syncthreads();

        #pragma unroll 4
        for (int ci = 0; ci < 32; ci++) {
            float v[4][5];
            #pragma unroll
            for (int i = 0; i < 4; i++)
                #pragma unroll
                for (int k = 0; k < 5; k++)
                    v[i][k] = sin_[ci][2 * lg + 64 * i + k];
            #pragma unroll
            for (int j = 0; j < 4; j++)
                #pragma unroll
                for (int k = 0; k < 5; k++) {
                    float w = sw[(cidx * 4 + j) * 161 + ci * 5 + k];
                    #pragma unroll
                    for (int i = 0; i < 4; i++)
                        acc[j][i] += w * v[i][k];
                }
        }
    }

    #pragma unroll
    for (int j = 0; j < 4; j++) {
        int co = cg * 16 + cidx * 4 + j;
        float bias = eb2[e * 128 + co];
        #pragma unroll
        for (int i = 0; i < 4; i++) {
            int l = l0 + lg + 32 * i;
            if (l < L2E)
                g_e2[((size_t)t * 128 + co) * L2E + l] = fmaxf(acc[j][i] + bias, 0.0f);
        }
    }
}

// ---------------- 7) expert conv3: (128 -> 128), k=3, s=1, p=1, relu -----------
__global__ void econv3_kernel(const float* __restrict__ ew3, const float* __restrict__ eb3) {
    __shared__ float sin_[32][132];
    __shared__ float sw[16 * 97];
    int t  = blockIdx.z;
    int e  = g_ti[t];
    int l0 = blockIdx.x * 128;
    int cg = blockIdx.y;
    int tid = threadIdx.x;
    int lg  = tid & 31;
    int cidx = tid >> 5;

    float acc[4][4];
    #pragma unroll
    for (int j = 0; j < 4; j++)
        #pragma unroll
        for (int i = 0; i < 4; i++) acc[j][i] = 0.0f;

    const float* e2base = g_e2 + (size_t)t * 128 * L2E;

    for (int cb = 0; cb < 4; cb++) {
        __syncthreads();
        for (int i = tid; i < 32 * 130; i += 128) {
            int ci = i / 130, j = i % 130;
            int g = l0 - 1 + j;
            sin_[ci][j] = (g >= 0 && g < L2E) ? e2base[(cb * 32 + ci) * L2E + g] : 0.0f;
        }
        for (int i = tid; i < 16 * 96; i += 128) {
            int co = i / 96, r = i % 96;
            sw[co * 97 + r] = ew3[((e * 128 + cg * 16 + co) * 128 + cb * 32) * 3 + r];
        }
        __syncthreads();

        #pragma unroll 4
        for (int ci = 0; ci < 32; ci++) {
            float v[4][3];
            #pragma unroll
            for (int i = 0; i < 4; i++)
                #pragma unroll
                for (int k = 0; k < 3; k++)
                    v[i][k] = sin_[ci][lg + 32 * i + k];
            #pragma unroll
            for (int j = 0; j < 4; j++)
                #pragma unroll
                for (int k = 0; k < 3; k++) {
                    float w = sw[(cidx * 4 + j) * 97 + ci * 3 + k];
                    #pragma unroll
                    for (int i = 0; i < 4; i++)
                        acc[j][i] += w * v[i][k];
                }
        }
    }

    #pragma unroll
    for (int j = 0; j < 4; j++) {
        int co = cg * 16 + cidx * 4 + j;
        float bias = eb3[e * 128 + co];
        #pragma unroll
        for (int i = 0; i < 4; i++) {
            int l = l0 + lg + 32 * i;
            if (l < L2E)
                g_e3[((size_t)t * 128 + co) * L2E + l] = fmaxf(acc[j][i] + bias, 0.0f);
        }
    }
}

// ---------------- 8) top-2 weighted combine + adaptive max-pool (513 -> 256) ---
__global__ void pool_kernel(float* __restrict__ out) {
    int idx = blockIdx.x * blockDim.x + threadIdx.x;
    if (idx >= B * 128 * 256) return;
    int o  = idx & 255;
    int co = (idx >> 8) & 127;
    int b  = idx >> 15;
    float w0 = g_tw[b * 2 + 0];
    float w1 = g_tw[b * 2 + 1];
    const float* p0 = g_e3 + ((size_t)(b * 2 + 0) * 128 + co) * L2E;
    const float* p1 = g_e3 + ((size_t)(b * 2 + 1) * 128 + co) * L2E;
    int s  = (o * 513) >> 8;
    int en = (o * 513 + 513 + 255) >> 8;
    float m = -INFINITY;
    for (int l = s; l < en; l++)
        m = fmaxf(m, w0 * p0[l] + w1 * p1[l]);
    out[idx] = m;
}

// ---------------- launch --------------------------------------------------------
extern "C" void kernel_launch(void* const* d_in, const int* in_sizes, int n_in,
                              void* d_out, int out_size) {
    const float* x    = (const float*)d_in[0];
    const float* gw1  = (const float*)d_in[1];
    const float* gb1  = (const float*)d_in[2];
    const float* gw2  = (const float*)d_in[3];
    const float* gb2  = (const float*)d_in[4];
    const float* mw1  = (const float*)d_in[5];
    const float* mb1  = (const float*)d_in[6];
    const float* mw2  = (const float*)d_in[7];
    const float* mb2  = (const float*)d_in[8];
    const float* ew1  = (const float*)d_in[9];
    const float* eb1  = (const float*)d_in[10];
    const float* ew2  = (const float*)d_in[11];
    const float* eb2  = (const float*)d_in[12];
    const float* ew3  = (const float*)d_in[13];
    const float* eb3  = (const float*)d_in[14];
    float* out = (float*)d_out;

    fft_kernel<<<B, 512>>>(x);
    gconv1_kernel<<<dim3(17, B), 128>>>(gw1, gb1);
    zero_pooled_kernel<<<32, 256>>>();
    gconv2_pool_kernel<<<dim3(17, B, 2), 256>>>(gw2, gb2);
    gate_mlp_kernel<<<1, 128>>>(mw1, mb1, mw2, mb2, out, out_size);
    econv1_kernel<<<NTASK, 256>>>(ew1, eb1);
    econv2_kernel<<<dim3(5, 8, NTASK), 128>>>(ew2, eb2);
    econv3_kernel<<<dim3(5, 8, NTASK), 128>>>(ew3, eb3);
    pool_kernel<<<16384, 256>>>(out);
}

// round 3
// speedup vs baseline: 1.2310x; 1.2310x over previous
#include <cuda_runtime.h>
#include <math.h>

#define B 128
#define LSEQ 4096
#define NF 2049          // rfft bins
#define NFP 2052         // padded row stride for g_h1 (16B-aligned rows)
#define L1E 1025         // expert conv1 out length
#define L1P 1028         // padded stride
#define L2E 513          // expert conv2/conv3 out length
#define L2P 516          // padded stride
#define NTASK 256        // B * TOP_K

// ---------------- scratch (device globals; no allocations allowed) -------------
__device__ float g_fft[B * 2 * NF];          // windowed rfft, [b][re/im][f]
__device__ float g_h1 [B * 32 * NFP];        // gate conv1 out (padded rows)
__device__ float g_pooled[B * 64];           // gate conv2 mean-pool accum
__device__ float g_tw[NTASK];                // normalized top-2 weights
__device__ int   g_ti[NTASK];                // top-2 expert ids
__device__ float g_e1[NTASK * 64  * L1P];
__device__ float g_e2[NTASK * 128 * L2P];
__device__ float g_e3[NTASK * 128 * L2P];

// ---------------- 1) Hann window + 4096-pt radix-2 FFT (one block per row) -----
__global__ void fft_kernel(const float* __restrict__ x) {
    __shared__ float re[4096];
    __shared__ float im[4096];
    __shared__ float twr[2048];
    __shared__ float twi[2048];
    int b = blockIdx.x;
    const float* xb = x + b * LSEQ;

    for (int i = threadIdx.x; i < 2048; i += blockDim.x) {
        float si, sr;
        sincospif(-(float)i * (1.0f / 2048.0f), &si, &sr);
        twr[i] = sr; twi[i] = si;
    }
    for (int i = threadIdx.x; i < 4096; i += blockDim.x) {
        float w = 0.5f * (1.0f - cospif((float)i * (1.0f / 2048.0f)));
        int j = __brev((unsigned)i) >> 20;   // 12-bit reversal
        re[j] = xb[i] * w;
        im[j] = 0.0f;
    }
    __syncthreads();

    for (int s = 1; s <= 12; s++) {
        int half = 1 << (s - 1);
        int len  = 1 << s;
        int shft = 12 - s;
        for (int t = threadIdx.x; t < 2048; t += blockDim.x) {
            int g   = t >> (s - 1);
            int pos = t & (half - 1);
            int i0  = g * len + pos;
            int i1  = i0 + half;
            int j   = pos << shft;
            float sr = twr[j], si = twi[j];
            float ar = re[i1], ai = im[i1];
            float tr = ar * sr - ai * si;
            float ti = ar * si + ai * sr;
            float br = re[i0], bi = im[i0];
            re[i1] = br - tr; im[i1] = bi - ti;
            re[i0] = br + tr; im[i0] = bi + ti;
        }
        __syncthreads();
    }
    const float sc = 1.0f / 64.0f;   // ortho norm: 1/sqrt(4096)
    for (int f = threadIdx.x; f < NF; f += blockDim.x) {
        g_fft[(b * 2 + 0) * NF + f] = re[f] * sc;
        g_fft[(b * 2 + 1) * NF + f] = im[f] * sc;
    }
}

// ---------------- 2) gate conv1: (2 -> 32), k=5, s=1, p=2, relu ----------------
__global__ void gconv1_kernel(const float* __restrict__ w1, const float* __restrict__ b1) {
    __shared__ __align__(16) float sin_[2][1036];
    __shared__ float sw[32][11];
    __shared__ float sb[32];
    int b  = blockIdx.y;
    int l0 = blockIdx.x * 1024;
    int tid = threadIdx.x;   // 256

    for (int i = tid; i < 2 * 1032; i += 256) {
        int ci = i / 1032, j = i % 1032;
        int g = l0 + j - 2;
        sin_[ci][j] = (g >= 0 && g < NF) ? g_fft[(b * 2 + ci) * NF + g] : 0.0f;
    }
    for (int i = tid; i < 320; i += 256) sw[i / 10][i % 10] = w1[i];
    if (tid < 32) sb[tid] = b1[tid];
    __syncthreads();

    // v window: j = 4*tid + i + k, i<=3, k<=4 -> 8 floats
    float v[2][8];
    #pragma unroll
    for (int ci = 0; ci < 2; ci++) {
        float4 a = *(const float4*)&sin_[ci][4 * tid];
        float4 c = *(const float4*)&sin_[ci][4 * tid + 4];
        v[ci][0] = a.x; v[ci][1] = a.y; v[ci][2] = a.z; v[ci][3] = a.w;
        v[ci][4] = c.x; v[ci][5] = c.y; v[ci][6] = c.z; v[ci][7] = c.w;
    }

    #pragma unroll 4
    for (int co = 0; co < 32; co++) {
        float acc[4];
        #pragma unroll
        for (int i = 0; i < 4; i++) acc[i] = sb[co];
        #pragma unroll
        for (int ci = 0; ci < 2; ci++)
            #pragma unroll
            for (int k = 0; k < 5; k++) {
                float w = sw[co][ci * 5 + k];
                #pragma unroll
                for (int i = 0; i < 4; i++) acc[i] += w * v[ci][i + k];
            }
        float4 r;
        r.x = fmaxf(acc[0], 0.0f); r.y = fmaxf(acc[1], 0.0f);
        r.z = fmaxf(acc[2], 0.0f); r.w = fmaxf(acc[3], 0.0f);
        *(float4*)&g_h1[(b * 32 + co) * NFP + l0 + 4 * tid] = r;
    }

    // tail: l = 2048 handled by block x=1, tid 0 (j = 2048 - l0 + 2 + k = 1024 + k)
    if (blockIdx.x == 1 && tid == 0) {
        for (int co = 0; co < 32; co++) {
            float acc = sb[co];
            #pragma unroll
            for (int ci = 0; ci < 2; ci++)
                #pragma unroll
                for (int k = 0; k < 5; k++)
                    acc += sin_[ci][1024 + k] * sw[co][ci * 5 + k];
            g_h1[(b * 32 + co) * NFP + 2048] = fmaxf(acc, 0.0f);
        }
    }
}

__global__ void zero_pooled_kernel() {
    int i = blockIdx.x * blockDim.x + threadIdx.x;
    if (i < B * 64) g_pooled[i] = 0.0f;
}

// ---------------- 3) gate conv2 (32 -> 64, k5, p2) fused with mean pool --------
__global__ void gconv2_pool_kernel(const float* __restrict__ w2, const float* __restrict__ b2) {
    __shared__ __align__(16) float sin_[16][132];
    __shared__ float sw[64][81];
    int b   = blockIdx.y;
    int l0  = blockIdx.x * 128;
    int tid = threadIdx.x;
    int lane = tid & 31;
    int wid  = tid >> 5;               // warp owns co = wid*8 .. +7

    float acc[8][4];
    #pragma unroll
    for (int j = 0; j < 8; j++)
        #pragma unroll
        for (int i = 0; i < 4; i++) acc[j][i] = 0.0f;

    for (int cb = 0; cb < 2; cb++) {
        __syncthreads();
        for (int i = tid; i < 16 * 132; i += 256) {
            int ci = i / 132, j = i % 132;
            int g = l0 + j - 2;
            sin_[ci][j] = (g >= 0 && g < NF) ? g_h1[(b * 32 + cb * 16 + ci) * NFP + g] : 0.0f;
        }
        for (int i = tid; i < 64 * 80; i += 256) {
            int co = i / 80, r = i % 80;
            sw[co][r] = w2[co * 160 + cb * 80 + r];
        }
        __syncthreads();

        #pragma unroll 2
        for (int ci = 0; ci < 16; ci++) {
            float4 a = *(const float4*)&sin_[ci][4 * lane];
            float4 c = *(const float4*)&sin_[ci][4 * lane + 4];
            float v[8] = {a.x, a.y, a.z, a.w, c.x, c.y, c.z, c.w};
            #pragma unroll
            for (int j = 0; j < 8; j++) {
                #pragma unroll
                for (int k = 0; k < 5; k++) {
                    float w = sw[wid * 8 + j][ci * 5 + k];
                    #pragma unroll
                    for (int i = 0; i < 4; i++)
                        acc[j][i] += w * v[i + k];
                }
            }
        }
    }

    #pragma unroll
    for (int j = 0; j < 8; j++) {
        int co = wid * 8 + j;
        float bias = b2[co];
        float part = 0.0f;
        #pragma unroll
        for (int i = 0; i < 4; i++) {
            int l = l0 + 4 * lane + i;
            if (l < NF) part += fmaxf(acc[j][i] + bias, 0.0f);
        }
        #pragma unroll
        for (int off = 16; off; off >>= 1)
            part += __shfl_down_sync(0xffffffffu, part, off, 32);
        if (lane == 0) atomicAdd(&g_pooled[b * 64 + co], part);
    }
}

// ---------------- 4) router MLP + softmax + top2 + aux (one block) -------------
__global__ void gate_mlp_kernel(const float* __restrict__ w1, const float* __restrict__ b1,
                                const float* __restrict__ w2, const float* __restrict__ b2,
                                float* __restrict__ out, int out_size) {
    int b = threadIdx.x;   // 128
    const float inv = 1.0f / 2049.0f;
    float p[64];
    #pragma unroll
    for (int i = 0; i < 64; i++) p[i] = g_pooled[b * 64 + i] * inv;

    float lg[8];
    #pragma unroll
    for (int e = 0; e < 8; e++) lg[e] = b2[e];

    for (int j = 0; j < 128; j++) {
        float h0 = 0.f, h1 = 0.f, h2 = 0.f, h3 = 0.f;
        #pragma unroll
        for (int i = 0; i < 64; i += 4) {
            h0 += p[i + 0] * w1[j * 64 + i + 0];
            h1 += p[i + 1] * w1[j * 64 + i + 1];
            h2 += p[i + 2] * w1[j * 64 + i + 2];
            h3 += p[i + 3] * w1[j * 64 + i + 3];
        }
        float h = fmaxf((h0 + h1) + (h2 + h3) + b1[j], 0.0f);
        #pragma unroll
        for (int e = 0; e < 8; e++) lg[e] += h * w2[e * 128 + j];
    }

    float m = lg[0];
    #pragma unroll
    for (int e = 1; e < 8; e++) m = fmaxf(m, lg[e]);
    float rw[8], s = 0.0f;
    #pragma unroll
    for (int e = 0; e < 8; e++) { rw[e] = expf(lg[e] - m); s += rw[e]; }
    float invs = 1.0f / s;
    #pragma unroll
    for (int e = 0; e < 8; e++) rw[e] *= invs;

    int i0 = 0;
    #pragma unroll
    for (int e = 1; e < 8; e++) if (rw[e] > rw[i0]) i0 = e;
    int i1 = (i0 == 0) ? 1 : 0;
    #pragma unroll
    for (int e = 0; e < 8; e++) if (e != i1 && e != i0 && rw[e] > rw[i1]) i1 = e;

    float t0 = rw[i0], t1 = rw[i1];
    float tn = 1.0f / (t0 + t1);
    g_ti[b * 2 + 0] = i0; g_ti[b * 2 + 1] = i1;
    g_tw[b * 2 + 0] = t0 * tn; g_tw[b * 2 + 1] = t1 * tn;

    __shared__ float srw[8], slg[8];
    if (b < 8) { srw[b] = 0.0f; slg[b] = 0.0f; }
    __syncthreads();
    #pragma unroll
    for (int e = 0; e < 8; e++) {
        atomicAdd(&srw[e], rw[e]);
        atomicAdd(&slg[e], lg[e]);
    }
    __syncthreads();
    if (b == 0) {
        float aux = 0.0f;
        #pragma unroll
        for (int e = 0; e < 8; e++)
            aux += (srw[e] * (1.0f / 128.0f)) * (slg[e] * (1.0f / 128.0f));
        out[out_size - 1] = 0.01f * 8.0f * aux;
    }
}

// ---------------- 5) expert conv1: (2 -> 64), k=7, s=2, p=3, relu --------------
__global__ void econv1_kernel(const float* __restrict__ ew1, const float* __restrict__ eb1) {
    __shared__ __align__(16) float sin_[2][2056];
    __shared__ float sw[64][16];
    __shared__ float sb[64];
    int t = blockIdx.x;
    int b = t >> 1;
    int e = g_ti[t];
    int tid = threadIdx.x;   // 256

    for (int i = tid; i < 2 * 2056; i += 256) {
        int ci = i / 2056, j = i % 2056;
        int g = j - 3;
        sin_[ci][j] = (g >= 0 && g < NF) ? g_fft[(b * 2 + ci) * NF + g] : 0.0f;
    }
    for (int i = tid; i < 64 * 14; i += 256) sw[i / 14][i % 14] = ew1[e * 896 + i];
    if (tid < 64) sb[tid] = eb1[e * 64 + tid];
    __syncthreads();

    // window for l = 4*tid..4*tid+3: j = 8*tid + 2i + k, i<=3, k<=6 -> needs 13 floats.
    // Load 16 (4x float4): 8*tid+15 <= 2055 < 2056 in bounds.
    float v[2][16];
    #pragma unroll
    for (int ci = 0; ci < 2; ci++) {
        float4 a = *(const float4*)&sin_[ci][8 * tid];
        float4 c = *(const float4*)&sin_[ci][8 * tid + 4];
        float4 d = *(const float4*)&sin_[ci][8 * tid + 8];
        float4 f = *(const float4*)&sin_[ci][8 * tid + 12];
        v[ci][0]=a.x;  v[ci][1]=a.y;  v[ci][2]=a.z;  v[ci][3]=a.w;
        v[ci][4]=c.x;  v[ci][5]=c.y;  v[ci][6]=c.z;  v[ci][7]=c.w;
        v[ci][8]=d.x;  v[ci][9]=d.y;  v[ci][10]=d.z; v[ci][11]=d.w;
        v[ci][12]=f.x; v[ci][13]=f.y; v[ci][14]=f.z; v[ci][15]=f.w;
    }

    #pragma unroll 2
    for (int co = 0; co < 64; co++) {
        float acc[4];
        #pragma unroll
        for (int i = 0; i < 4; i++) acc[i] = sb[co];
        #pragma unroll
        for (int ci = 0; ci < 2; ci++)
            #pragma unroll
            for (int k = 0; k < 7; k++) {
                float w = sw[co][ci * 7 + k];
                #pragma unroll
                for (int i = 0; i < 4; i++) acc[i] += w * v[ci][2 * i + k];
            }
        float4 r;
        r.x = fmaxf(acc[0], 0.0f); r.y = fmaxf(acc[1], 0.0f);
        r.z = fmaxf(acc[2], 0.0f); r.w = fmaxf(acc[3], 0.0f);
        *(float4*)&g_e1[((size_t)t * 64 + co) * L1P + 4 * tid] = r;
    }

    // tail l = 1024: g = 2045+k -> j = 2048+k
    if (tid < 64) {
        int co = tid;
        float acc = sb[co];
        #pragma unroll
        for (int ci = 0; ci < 2; ci++)
            #pragma unroll
            for (int k = 0; k < 7; k++)
                acc += sin_[ci][2048 + k] * sw[co][ci * 7 + k];
        g_e1[((size_t)t * 64 + co) * L1P + 1024] = fmaxf(acc, 0.0f);
    }
}

// ---------------- 6) expert conv2: (64 -> 128), k=5, s=2, p=2, relu ------------
__global__ void econv2_kernel(const float* __restrict__ ew2, const float* __restrict__ eb2) {
    __shared__ __align__(16) float sin_[16][260];
    __shared__ float sw[64][81];
    int t  = blockIdx.z;
    int e  = g_ti[t];
    int l0 = blockIdx.x * 128;
    int cgrp = blockIdx.y;             // co base = cgrp*64
    int tid = threadIdx.x;
    int lane = tid & 31;
    int wid  = tid >> 5;

    float acc[8][4];
    #pragma unroll
    for (int j = 0; j < 8; j++)
        #pragma unroll
        for (int i = 0; i < 4; i++) acc[j][i] = 0.0f;

    const float* e1base = g_e1 + (size_t)t * 64 * L1P;

    for (int cb = 0; cb < 4; cb++) {
        __syncthreads();
        for (int i = tid; i < 16 * 260; i += 256) {
            int ci = i / 260, j = i % 260;
            int g = 2 * l0 - 2 + j;
            sin_[ci][j] = (g >= 0 && g < L1E) ? e1base[(cb * 16 + ci) * L1P + g] : 0.0f;
        }
        for (int i = tid; i < 64 * 80; i += 256) {
            int co = i / 80, r = i % 80;
            sw[co][r] = ew2[((e * 128 + cgrp * 64 + co) * 64 + cb * 16) * 5 + r];
        }
        __syncthreads();

        #pragma unroll 2
        for (int ci = 0; ci < 16; ci++) {
            // j = 8*lane + 2i + k, i<=3, k<=4 -> max +10, 12 floats enough
            float4 a = *(const float4*)&sin_[ci][8 * lane];
            float4 c = *(const float4*)&sin_[ci][8 * lane + 4];
            float4 d = *(const float4*)&sin_[ci][8 * lane + 8];
            float v[12] = {a.x,a.y,a.z,a.w, c.x,c.y,c.z,c.w, d.x,d.y,d.z,d.w};
            #pragma unroll
            for (int j = 0; j < 8; j++) {
                #pragma unroll
                for (int k = 0; k < 5; k++) {
                    float w = sw[wid * 8 + j][ci * 5 + k];
                    #pragma unroll
                    for (int i = 0; i < 4; i++)
                        acc[j][i] += w * v[2 * i + k];
                }
            }
        }
    }

    #pragma unroll
    for (int j = 0; j < 8; j++) {
        int co = cgrp * 64 + wid * 8 + j;
        float bias = eb2[e * 128 + co];
        int lbase = l0 + 4 * lane;
        float* dst = &g_e2[((size_t)t * 128 + co) * L2P + lbase];
        if (lbase + 3 < L2E) {
            float4 r;
            r.x = fmaxf(acc[j][0] + bias, 0.0f);
            r.y = fmaxf(acc[j][1] + bias, 0.0f);
            r.z = fmaxf(acc[j][2] + bias, 0.0f);
            r.w = fmaxf(acc[j][3] + bias, 0.0f);
            *(float4*)dst = r;
        } else {
            #pragma unroll
            for (int i = 0; i < 4; i++)
                if (lbase + i < L2E) dst[i] = fmaxf(acc[j][i] + bias, 0.0f);
        }
    }
}

// ---------------- 7) expert conv3: (128 -> 128), k=3, s=1, p=1, relu -----------
__global__ void econv3_kernel(const float* __restrict__ ew3, const float* __restrict__ eb3) {
    __shared__ __align__(16) float sin_[16][132];
    __shared__ float sw[64][49];
    int t  = blockIdx.z;
    int e  = g_ti[t];
    int l0 = blockIdx.x * 128;
    int cgrp = blockIdx.y;
    int tid = threadIdx.x;
    int lane = tid & 31;
    int wid  = tid >> 5;

    float acc[8][4];
    #pragma unroll
    for (int j = 0; j < 8; j++)
        #pragma unroll
        for (int i = 0; i < 4; i++) acc[j][i] = 0.0f;

    const float* e2base = g_e2 + (size_t)t * 128 * L2P;

    for (int cb = 0; cb < 8; cb++) {
        __syncthreads();
        for (int i = tid; i < 16 * 132; i += 256) {
            int ci = i / 132, j = i % 132;
            int g = l0 - 1 + j;
            sin_[ci][j] = (g >= 0 && g < L2E) ? e2base[(cb * 16 + ci) * L2P + g] : 0.0f;
        }
        for (int i = tid; i < 64 * 48; i += 256) {
            int co = i / 48, r = i % 48;
            sw[co][r] = ew3[((e * 128 + cgrp * 64 + co) * 128 + cb * 16) * 3 + r];
        }
        __syncthreads();

        #pragma unroll 2
        for (int ci = 0; ci < 16; ci++) {
            // j = 4*lane + i + k, i<=3, k<=2 -> max +5, 8 floats enough
            float4 a = *(const float4*)&sin_[ci][4 * lane];
            float4 c = *(const float4*)&sin_[ci][4 * lane + 4];
            float v[8] = {a.x,a.y,a.z,a.w, c.x,c.y,c.z,c.w};
            #pragma unroll
            for (int j = 0; j < 8; j++) {
                #pragma unroll
                for (int k = 0; k < 3; k++) {
                    float w = sw[wid * 8 + j][ci * 3 + k];
                    #pragma unroll
                    for (int i = 0; i < 4; i++)
                        acc[j][i] += w * v[i + k];
                }
            }
        }
    }

    #pragma unroll
    for (int j = 0; j < 8; j++) {
        int co = cgrp * 64 + wid * 8 + j;
        float bias = eb3[e * 128 + co];
        int lbase = l0 + 4 * lane;
        float* dst = &g_e3[((size_t)t * 128 + co) * L2P + lbase];
        if (lbase + 3 < L2E) {
            float4 r;
            r.x = fmaxf(acc[j][0] + bias, 0.0f);
            r.y = fmaxf(acc[j][1] + bias, 0.0f);
            r.z = fmaxf(acc[j][2] + bias, 0.0f);
            r.w = fmaxf(acc[j][3] + bias, 0.0f);
            *(float4*)dst = r;
        } else {
            #pragma unroll
            for (int i = 0; i < 4; i++)
                if (lbase + i < L2E) dst[i] = fmaxf(acc[j][i] + bias, 0.0f);
        }
    }
}

// ---------------- 8) top-2 weighted combine + adaptive max-pool (513 -> 256) ---
__global__ void pool_kernel(float* __restrict__ out) {
    int idx = blockIdx.x * blockDim.x + threadIdx.x;
    if (idx >= B * 128 * 256) return;
    int o  = idx & 255;
    int co = (idx >> 8) & 127;
    int b  = idx >> 15;
    float w0 = g_tw[b * 2 + 0];
    float w1 = g_tw[b * 2 + 1];
    const float* p0 = g_e3 + ((size_t)(b * 2 + 0) * 128 + co) * L2P;
    const float* p1 = g_e3 + ((size_t)(b * 2 + 1) * 128 + co) * L2P;
    int s  = (o * 513) >> 8;
    int en = (o * 513 + 513 + 255) >> 8;
    float m = -INFINITY;
    for (int l = s; l < en; l++)
        m = fmaxf(m, w0 * p0[l] + w1 * p1[l]);
    out[idx] = m;
}

// ---------------- launch --------------------------------------------------------
extern "C" void kernel_launch(void* const* d_in, const int* in_sizes, int n_in,
                              void* d_out, int out_size) {
    const float* x    = (const float*)d_in[0];
    const float* gw1  = (const float*)d_in[1];
    const float* gb1  = (const float*)d_in[2];
    const float* gw2  = (const float*)d_in[3];
    const float* gb2  = (const float*)d_in[4];
    const float* mw1  = (const float*)d_in[5];
    const float* mb1  = (const float*)d_in[6];
    const float* mw2  = (const float*)d_in[7];
    const float* mb2  = (const float*)d_in[8];
    const float* ew1  = (const float*)d_in[9];
    const float* eb1  = (const float*)d_in[10];
    const float* ew2  = (const float*)d_in[11];
    const float* eb2  = (const float*)d_in[12];
    const float* ew3  = (const float*)d_in[13];
    const float* eb3  = (const float*)d_in[14];
    float* out = (float*)d_out;

    fft_kernel<<<B, 512>>>(x);
    gconv1_kernel<<<dim3(2, B), 256>>>(gw1, gb1);
    zero_pooled_kernel<<<32, 256>>>();
    gconv2_pool_kernel<<<dim3(17, B), 256>>>(gw2, gb2);
    gate_mlp_kernel<<<1, 128>>>(mw1, mb1, mw2, mb2, out, out_size);
    econv1_kernel<<<NTASK, 256>>>(ew1, eb1);
    econv2_kernel<<<dim3(5, 2, NTASK), 256>>>(ew2, eb2);
    econv3_kernel<<<dim3(5, 2, NTASK), 256>>>(ew3, eb3);
    pool_kernel<<<16384, 256>>>(out);
}